// round 14
// baseline (speedup 1.0000x reference)
#include <cuda_runtime.h>
#include <cstdint>

#define B_ 64
#define I_ 64
#define O_ 64
#define T_ 8192
#define KDIM 192      // I_*3
#define NH 64
#define MW 32
#define QD 320

#define TT 256
#define XS 264                 // x tile row stride: 264 % 32 == 8 -> conflict-free
#define CONV_THREADS 512
#define GRID 152
#define TILES_TOTAL (B_*(T_/TT))   // 2048
#define AF_FLOATS 12288        // A fragment region; also exactly 64*192 for ctrl_w staging
#define XT_FLOATS (I_*XS)      // 16896
#define SMEM_FLOATS (AF_FLOATS + 64 + 2*XT_FLOATS)   // 46144
#define SMEM_BYTES (SMEM_FLOATS*4)                   // 184576

__device__ __forceinline__ float sigmoidf_(float x){ return 1.f/(1.f+expf(-x)); }
__device__ __forceinline__ float siluf_(float x){ return x * sigmoidf_(x); }
__device__ __forceinline__ uint32_t f2tf32(float x){
  uint32_t r; asm("cvt.rna.tf32.f32 %0, %1;" : "=r"(r) : "f"(x)); return r;
}
__device__ __forceinline__ float f2tf32f(float x){
  uint32_t r; asm("cvt.rna.tf32.f32 %0, %1;" : "=r"(r) : "f"(x));
  return __uint_as_float(r);
}

__device__ __forceinline__ void prefetch_tile(const float* __restrict__ x, int ti,
                                              float* __restrict__ sXb, int tid) {
  int bb = ti >> 5;
  int t0 = (ti & 31) << 8;
  const float* xb = x + (size_t)bb * (I_*T_);
  #pragma unroll
  for (int j = 0; j < 9; ++j) {
    int c = tid + j*CONV_THREADS;
    if (c < I_*66) {
      int row = c / 66;
      int jc = c - 66*row;
      int tg = t0 - 4 + jc*4;
      float* dst = sXb + row*XS + jc*4;
      if (tg >= 0 && tg <= T_-4) {
        unsigned sa = (unsigned)__cvta_generic_to_shared(dst);
        asm volatile("cp.async.cg.shared.global [%0], [%1], 16;"
                     :: "r"(sa), "l"(xb + (size_t)row*T_ + tg));
      } else {
        *reinterpret_cast<float4*>(dst) = make_float4(0.f,0.f,0.f,0.f);
      }
    }
  }
}

__global__ __launch_bounds__(CONV_THREADS, 1)
void fused_kernel(const float* __restrict__ x, float* __restrict__ out,
    const float* __restrict__ grads, const float* __restrict__ q_ema,
    const float* __restrict__ W,
    const float* __restrict__ conv_w, const float* __restrict__ conv_b,
    const float* __restrict__ ctrl_w, const float* __restrict__ ctrl_b,
    const float* __restrict__ cw_w, const float* __restrict__ cw_b,
    const float* __restrict__ cb_w, const float* __restrict__ cb_b,
    const float* __restrict__ cf_w, const float* __restrict__ cf_b,
    const float* __restrict__ tau_w1, const float* __restrict__ tau_b1,
    const float* __restrict__ tau_w2, const float* __restrict__ tau_b2,
    const int* __restrict__ trigger)
{
  extern __shared__ float smem[];
  float* sAf   = smem;                   // ctrl_w staging (prep) -> A fragments (conv)
  float* sBias = smem + AF_FLOATS;       // [64]
  float* sX0   = sBias + 64;             // [64][264]
  float* sX1   = sX0 + XT_FLOATS;

  __shared__ float s_rep[O_*68];
  __shared__ float s_q[QD];
  __shared__ float s_red[O_];
  __shared__ float s_tau;
  __shared__ float s_att[MW];
  __shared__ int   s_idx[3];
  __shared__ float s_v[3];

  int tid = threadIdx.x, bid = blockIdx.x;
  int start = (int)(((long long)bid    *TILES_TOTAL)/GRID);
  int end   = (int)(((long long)(bid+1)*TILES_TOTAL)/GRID);

  // kick off first two x-tile loads; their DRAM latency overlaps all of prep
  prefetch_tile(x, start, sX0, tid);
  asm volatile("cp.async.commit_group;");
  if (start + 1 < end) prefetch_tile(x, start+1, sX1, tid);
  asm volatile("cp.async.commit_group;");

  // ---- stage ctrl_w into sAf, coalesced, with per-row rotation swizzle ----
  for (int i4 = tid; i4 < NH*48; i4 += CONV_THREADS) {
    int h = i4 / 48, j4 = i4 - h*48;
    int slot = j4 + ((h >> 3) & 7); if (slot >= 48) slot -= 48;
    reinterpret_cast<float4*>(sAf)[h*48 + slot] = reinterpret_cast<const float4*>(ctrl_w)[i4];
  }
  __syncthreads();

  // ---- rep = silu(g @ ctrl_w.T + ctrl_b): thread -> (o, 8 h's) ----
  {
    int o = tid >> 3, hb = (tid & 7) << 3;
    int rot = tid & 7;
    const float4* g4 = reinterpret_cast<const float4*>(grads + o*KDIM);
    float acc[8];
    #pragma unroll
    for (int hh = 0; hh < 8; ++hh) acc[hh] = ctrl_b[hb+hh];
    #pragma unroll 4
    for (int j4 = 0; j4 < 48; ++j4) {
      float4 gv = __ldg(g4 + j4);
      int slot = j4 + rot; if (slot >= 48) slot -= 48;
      #pragma unroll
      for (int hh = 0; hh < 8; ++hh) {
        float4 wv = reinterpret_cast<const float4*>(sAf)[(hb+hh)*48 + slot];
        acc[hh] += gv.x*wv.x + gv.y*wv.y + gv.z*wv.z + gv.w*wv.w;
      }
    }
    #pragma unroll
    for (int hh = 0; hh < 8; ++hh) s_rep[o*68 + hb + hh] = siluf_(acc[hh]);
  }
  __syncthreads();

  // ---- heads ----
  if (tid < 192) {                 // w head
    int o = tid/3, k = tid - 3*(tid/3);
    const float* r = s_rep + o*68;
    const float* w = cw_w + k*NH;
    float s = cw_b[k];
    #pragma unroll 8
    for (int h = 0; h < NH; ++h) s += r[h]*w[h];
    s_q[o*3+k] = s;
  } else if (tid < 256) {          // b head
    int o = tid - 192;
    const float* r = s_rep + o*68;
    float s = cb_b[0];
    #pragma unroll 8
    for (int h = 0; h < NH; ++h) s += r[h]*cb_w[h];
    s_q[192+o] = s;
  } else if (tid < 320) {          // f head
    int o = tid - 256;
    const float* r = s_rep + o*68;
    float s = cf_b[0];
    #pragma unroll 8
    for (int h = 0; h < NH; ++h) s += r[h]*cf_w[h];
    s_q[256+o] = s;
  } else if (tid < 384) {          // tau head
    int o = tid - 320;
    const float* r = s_rep + o*68;
    float acc = tau_b2[0];
    for (int j = 0; j < 16; ++j) {
      float s = tau_b1[j];
      const float* w = tau_w1 + j*NH;
      #pragma unroll 8
      for (int h = 0; h < NH; ++h) s += r[h]*w[h];
      acc += siluf_(s)*tau_w2[j];
    }
    s_red[o] = sigmoidf_(acc);
  }
  __syncthreads();
  if (tid == 0) {
    float m = 0.f;
    for (int o = 0; o < O_; ++o) m += s_red[o];
    s_tau = (m * (1.f/64.f))*0.5f + 0.5f;
  }
  __syncthreads();

  if (tid < QD) s_q[tid] = 0.85f*s_q[tid] + 0.15f*q_ema[tid];  // EMA mix
  __syncthreads();

  if (trigger[0] == 1) {
    if (tid < MW) {
      float s = 0.f;
      for (int d = 0; d < QD; ++d) s += s_q[d]*W[d*MW + tid];
      s_att[tid] = s*2.0f;   // / TEMP (0.5)
    }
    __syncthreads();
    if (tid == 0) {
      float mx = s_att[0];
      for (int m = 1; m < MW; ++m) mx = fmaxf(mx, s_att[m]);
      float sum = 0.f;
      for (int m = 0; m < MW; ++m) { float e = expf(s_att[m]-mx); s_att[m] = e; sum += e; }
      float inv = 1.f/sum;
      for (int m = 0; m < MW; ++m) s_att[m] *= inv;
      for (int j = 0; j < 3; ++j) {     // top-3, lower index wins ties (matches jax top_k)
        float best = -1e30f; int bi = 0;
        for (int m = 0; m < MW; ++m) if (s_att[m] > best) { best = s_att[m]; bi = m; }
        s_v[j] = best; s_idx[j] = bi; s_att[bi] = -1e30f;
      }
    }
    __syncthreads();
    float tau = s_tau;
    if (tid < QD) {
      float old = s_v[0]*W[tid*MW+s_idx[0]] + s_v[1]*W[tid*MW+s_idx[1]] + s_v[2]*W[tid*MW+s_idx[2]];
      s_q[tid] = tau*s_q[tid] + (1.f-tau)*old;
    }
    __syncthreads();
  }

  // ---- emit bias + fragment-ordered A into sAf (overwrites ctrl_w staging) ----
  if (tid < O_) sBias[tid] = conv_b[tid]*s_q[192+tid]*s_q[256+tid];
  #pragma unroll 4
  for (int idx = tid; idx < O_*KDIM; idx += CONV_THREADS) {
    int o = idx / KDIM;
    int r = idx - o*KDIM;
    int i = r / 3;
    int k = r - i*3;
    float v = conv_w[idx] * s_q[o*3+k] * s_q[256+o];
    int kap = k*64 + i;
    int kk = kap >> 3, c = kap & 7;
    int t4 = c & 3, half = c >> 2;
    int wm = o >> 5, mt = (o >> 4) & 1, g = o & 7, rh = (o >> 3) & 1;
    int fi = ((((wm*24 + kk)*2 + mt)*32) + (g*4 + t4))*4 + half*2 + rh;
    sAf[fi] = __uint_as_float(f2tf32(v));
  }
  __syncthreads();

  // ================== CONV mainloop ==================
  int wid = tid >> 5, lane = tid & 31;
  int g  = lane >> 2, t4 = lane & 3;
  int warp_m = wid & 1, warp_n = wid >> 1;     // 2 x 8 warps
  const float* sAfw = sAf + warp_m*6144 + lane*4;
  int tloc3 = warp_n*32 + g + 3;

  for (int ti = start; ti < end; ++ti) {
    float* sx = ((ti - start) & 1) ? sX1 : sX0;
    if (ti + 1 < end) { asm volatile("cp.async.wait_group 1;"); }
    else              { asm volatile("cp.async.wait_group 0;"); }
    __syncthreads();

    // ---- one-pass in-place tf32 rounding of the tile (idempotent for MMA) ----
    {
      float4* p = reinterpret_cast<float4*>(sx);
      #pragma unroll
      for (int j = 0; j < 9; ++j) {
        int i4 = tid + j*CONV_THREADS;
        if (i4 < XT_FLOATS/4) {
          float4 v = p[i4];
          v.x = f2tf32f(v.x); v.y = f2tf32f(v.y);
          v.z = f2tf32f(v.z); v.w = f2tf32f(v.w);
          p[i4] = v;
        }
      }
    }
    __syncthreads();

    float c[2][4][4];
    #pragma unroll
    for (int mt = 0; mt < 2; ++mt)
      #pragma unroll
      for (int nt = 0; nt < 4; ++nt)
        { c[mt][nt][0]=0.f; c[mt][nt][1]=0.f; c[mt][nt][2]=0.f; c[mt][nt][3]=0.f; }

    const float* pB = sx + t4*XS + tloc3;

    #pragma unroll
    for (int kk = 0; kk < 24; ++kk) {
      const int ktap = kk >> 3;   // compile-time after unroll
      const int ic   = kk & 7;
      float4 a0 = *reinterpret_cast<const float4*>(sAfw + (kk*2+0)*128);
      float4 a1 = *reinterpret_cast<const float4*>(sAfw + (kk*2+1)*128);
      const float* pb = pB + ic*(8*XS) + ktap;
      uint32_t b0[4], b1[4];
      #pragma unroll
      for (int nt = 0; nt < 4; ++nt) {
        b0[nt] = __float_as_uint(pb[nt*8]);          // already tf32-rounded
        b1[nt] = __float_as_uint(pb[4*XS + nt*8]);
      }
      #pragma unroll
      for (int nt = 0; nt < 4; ++nt) {
        asm("mma.sync.aligned.m16n8k8.row.col.f32.tf32.tf32.f32 "
            "{%0,%1,%2,%3}, {%4,%5,%6,%7}, {%8,%9}, {%0,%1,%2,%3};"
            : "+f"(c[0][nt][0]), "+f"(c[0][nt][1]), "+f"(c[0][nt][2]), "+f"(c[0][nt][3])
            : "r"(__float_as_uint(a0.x)), "r"(__float_as_uint(a0.y)),
              "r"(__float_as_uint(a0.z)), "r"(__float_as_uint(a0.w)),
              "r"(b0[nt]), "r"(b1[nt]));
        asm("mma.sync.aligned.m16n8k8.row.col.f32.tf32.tf32.f32 "
            "{%0,%1,%2,%3}, {%4,%5,%6,%7}, {%8,%9}, {%0,%1,%2,%3};"
            : "+f"(c[1][nt][0]), "+f"(c[1][nt][1]), "+f"(c[1][nt][2]), "+f"(c[1][nt][3])
            : "r"(__float_as_uint(a1.x)), "r"(__float_as_uint(a1.y)),
              "r"(__float_as_uint(a1.z)), "r"(__float_as_uint(a1.w)),
              "r"(b0[nt]), "r"(b1[nt]));
      }
    }
    __syncthreads();  // done reading sx

    if (ti + 2 < end) {
      prefetch_tile(x, ti+2, sx, tid);
      asm volatile("cp.async.commit_group;");
    }

    // epilogue
    int bb = ti >> 5;
    int t0 = (ti & 31) << 8;
    float* outb = out + (size_t)bb*(O_*T_) + t0 + warp_n*32 + t4*2;
    #pragma unroll
    for (int mt = 0; mt < 2; ++mt) {
      int o0 = warp_m*32 + mt*16 + g;
      float bv0 = sBias[o0], bv1 = sBias[o0+8];
      float* p0 = outb + (size_t)o0*T_;
      float* p1 = p0 + (size_t)8*T_;
      #pragma unroll
      for (int nt = 0; nt < 4; ++nt) {
        *reinterpret_cast<float2*>(p0 + nt*8) = make_float2(c[mt][nt][0]+bv0, c[mt][nt][1]+bv0);
        *reinterpret_cast<float2*>(p1 + nt*8) = make_float2(c[mt][nt][2]+bv1, c[mt][nt][3]+bv1);
      }
    }
  }
}

// -------------------- launch --------------------
extern "C" void kernel_launch(void* const* d_in, const int* in_sizes, int n_in,
                              void* d_out, int out_size) {
  const float* x      = (const float*)d_in[0];
  const float* grads  = (const float*)d_in[1];
  const float* q_ema  = (const float*)d_in[2];
  const float* W      = (const float*)d_in[3];
  const float* conv_w = (const float*)d_in[4];
  const float* conv_b = (const float*)d_in[5];
  const float* ctrl_w = (const float*)d_in[6];
  const float* ctrl_b = (const float*)d_in[7];
  const float* cw_w   = (const float*)d_in[8];
  const float* cw_b   = (const float*)d_in[9];
  const float* cb_w   = (const float*)d_in[10];
  const float* cb_b   = (const float*)d_in[11];
  const float* cf_w   = (const float*)d_in[12];
  const float* cf_b   = (const float*)d_in[13];
  const float* tau_w1 = (const float*)d_in[14];
  const float* tau_b1 = (const float*)d_in[15];
  const float* tau_w2 = (const float*)d_in[16];
  const float* tau_b2 = (const float*)d_in[17];
  const int*   trig   = (const int*)d_in[18];
  float* out = (float*)d_out;

  cudaFuncSetAttribute(fused_kernel, cudaFuncAttributeMaxDynamicSharedMemorySize, SMEM_BYTES);
  fused_kernel<<<GRID, CONV_THREADS, SMEM_BYTES>>>(x, out, grads, q_ema, W, conv_w, conv_b,
      ctrl_w, ctrl_b, cw_w, cw_b, cb_w, cb_b, cf_w, cf_b,
      tau_w1, tau_b1, tau_w2, tau_b2, trig);
}

// round 15
// speedup vs baseline: 1.0069x; 1.0069x over previous
#include <cuda_runtime.h>
#include <cstdint>

#define B_ 64
#define I_ 64
#define O_ 64
#define T_ 8192
#define KDIM 192      // I_*3
#define NH 64
#define MW 32
#define QD 320

#define TT 256
#define XS 264                 // x tile row stride: 264 % 32 == 8 -> conflict-free
#define CONV_THREADS 512
#define GRID 152
#define TILES_TOTAL (B_*(T_/TT))   // 2048
#define AF_FLOATS 12288        // A fragment region; also exactly 64*192 for ctrl_w staging
#define XT_FLOATS (I_*XS)      // 16896
#define SMEM_FLOATS (AF_FLOATS + 64 + 2*XT_FLOATS)   // 46144
#define SMEM_BYTES (SMEM_FLOATS*4)                   // 184576

__device__ __forceinline__ float sigmoidf_(float x){ return 1.f/(1.f+expf(-x)); }
__device__ __forceinline__ float siluf_(float x){ return x * sigmoidf_(x); }
__device__ __forceinline__ uint32_t f2tf32(float x){
  uint32_t r; asm("cvt.rna.tf32.f32 %0, %1;" : "=r"(r) : "f"(x)); return r;
}
__device__ __forceinline__ float f2tf32f(float x){
  uint32_t r; asm("cvt.rna.tf32.f32 %0, %1;" : "=r"(r) : "f"(x));
  return __uint_as_float(r);
}

__device__ __forceinline__ void prefetch_tile(const float* __restrict__ x, int ti,
                                              float* __restrict__ sXb, int tid) {
  int bb = ti >> 5;
  int t0 = (ti & 31) << 8;
  const float* xb = x + (size_t)bb * (I_*T_);
  #pragma unroll
  for (int j = 0; j < 9; ++j) {
    int c = tid + j*CONV_THREADS;
    if (c < I_*66) {
      int row = c / 66;
      int jc = c - 66*row;
      int tg = t0 - 4 + jc*4;
      float* dst = sXb + row*XS + jc*4;
      if (tg >= 0 && tg <= T_-4) {
        unsigned sa = (unsigned)__cvta_generic_to_shared(dst);
        asm volatile("cp.async.cg.shared.global [%0], [%1], 16;"
                     :: "r"(sa), "l"(xb + (size_t)row*T_ + tg));
      } else {
        *reinterpret_cast<float4*>(dst) = make_float4(0.f,0.f,0.f,0.f);
      }
    }
  }
}

__global__ __launch_bounds__(CONV_THREADS, 1)
void fused_kernel(const float* __restrict__ x, float* __restrict__ out,
    const float* __restrict__ grads, const float* __restrict__ q_ema,
    const float* __restrict__ W,
    const float* __restrict__ conv_w, const float* __restrict__ conv_b,
    const float* __restrict__ ctrl_w, const float* __restrict__ ctrl_b,
    const float* __restrict__ cw_w, const float* __restrict__ cw_b,
    const float* __restrict__ cb_w, const float* __restrict__ cb_b,
    const float* __restrict__ cf_w, const float* __restrict__ cf_b,
    const float* __restrict__ tau_w1, const float* __restrict__ tau_b1,
    const float* __restrict__ tau_w2, const float* __restrict__ tau_b2,
    const int* __restrict__ trigger)
{
  extern __shared__ float smem[];
  float* sAf   = smem;                   // ctrl_w staging (prep) -> A fragments (conv)
  float* sBias = smem + AF_FLOATS;       // [64]
  float* sX0   = sBias + 64;             // [64][264]
  float* sX1   = sX0 + XT_FLOATS;

  __shared__ float s_rep[O_*68];
  __shared__ float s_q[QD];
  __shared__ float s_red[O_];
  __shared__ float s_tau;
  __shared__ float s_att[MW];
  __shared__ int   s_idx[3];
  __shared__ float s_v[3];

  int tid = threadIdx.x, bid = blockIdx.x;
  int start = (int)(((long long)bid    *TILES_TOTAL)/GRID);
  int end   = (int)(((long long)(bid+1)*TILES_TOTAL)/GRID);

  // ================== PREP FIRST (clean memory system, no cp.async contention) ==================

  // ---- stage ctrl_w into sAf, coalesced, with per-row rotation swizzle ----
  for (int i4 = tid; i4 < NH*48; i4 += CONV_THREADS) {
    int h = i4 / 48, j4 = i4 - h*48;
    int slot = j4 + ((h >> 3) & 7); if (slot >= 48) slot -= 48;
    reinterpret_cast<float4*>(sAf)[h*48 + slot] = reinterpret_cast<const float4*>(ctrl_w)[i4];
  }
  __syncthreads();

  // ---- rep = silu(g @ ctrl_w.T + ctrl_b): thread -> (o, 8 h's) ----
  {
    int o = tid >> 3, hb = (tid & 7) << 3;
    int rot = tid & 7;
    const float4* g4 = reinterpret_cast<const float4*>(grads + o*KDIM);
    float acc[8];
    #pragma unroll
    for (int hh = 0; hh < 8; ++hh) acc[hh] = ctrl_b[hb+hh];
    #pragma unroll 4
    for (int j4 = 0; j4 < 48; ++j4) {
      float4 gv = __ldg(g4 + j4);
      int slot = j4 + rot; if (slot >= 48) slot -= 48;
      #pragma unroll
      for (int hh = 0; hh < 8; ++hh) {
        float4 wv = reinterpret_cast<const float4*>(sAf)[(hb+hh)*48 + slot];
        acc[hh] += gv.x*wv.x + gv.y*wv.y + gv.z*wv.z + gv.w*wv.w;
      }
    }
    #pragma unroll
    for (int hh = 0; hh < 8; ++hh) s_rep[o*68 + hb + hh] = siluf_(acc[hh]);
  }
  __syncthreads();

  // ---- heads ----
  if (tid < 192) {                 // w head
    int o = tid/3, k = tid - 3*(tid/3);
    const float* r = s_rep + o*68;
    const float* w = cw_w + k*NH;
    float s = cw_b[k];
    #pragma unroll 8
    for (int h = 0; h < NH; ++h) s += r[h]*w[h];
    s_q[o*3+k] = s;
  } else if (tid < 256) {          // b head
    int o = tid - 192;
    const float* r = s_rep + o*68;
    float s = cb_b[0];
    #pragma unroll 8
    for (int h = 0; h < NH; ++h) s += r[h]*cb_w[h];
    s_q[192+o] = s;
  } else if (tid < 320) {          // f head
    int o = tid - 256;
    const float* r = s_rep + o*68;
    float s = cf_b[0];
    #pragma unroll 8
    for (int h = 0; h < NH; ++h) s += r[h]*cf_w[h];
    s_q[256+o] = s;
  } else if (tid < 384) {          // tau head
    int o = tid - 320;
    const float* r = s_rep + o*68;
    float acc = tau_b2[0];
    for (int j = 0; j < 16; ++j) {
      float s = tau_b1[j];
      const float* w = tau_w1 + j*NH;
      #pragma unroll 8
      for (int h = 0; h < NH; ++h) s += r[h]*w[h];
      acc += siluf_(s)*tau_w2[j];
    }
    s_red[o] = sigmoidf_(acc);
  }
  __syncthreads();
  if (tid == 0) {
    float m = 0.f;
    for (int o = 0; o < O_; ++o) m += s_red[o];
    s_tau = (m * (1.f/64.f))*0.5f + 0.5f;
  }
  __syncthreads();

  if (tid < QD) s_q[tid] = 0.85f*s_q[tid] + 0.15f*q_ema[tid];  // EMA mix
  __syncthreads();

  if (trigger[0] == 1) {
    if (tid < MW) {
      float s = 0.f;
      for (int d = 0; d < QD; ++d) s += s_q[d]*W[d*MW + tid];
      s_att[tid] = s*2.0f;   // / TEMP (0.5)
    }
    __syncthreads();
    if (tid == 0) {
      float mx = s_att[0];
      for (int m = 1; m < MW; ++m) mx = fmaxf(mx, s_att[m]);
      float sum = 0.f;
      for (int m = 0; m < MW; ++m) { float e = expf(s_att[m]-mx); s_att[m] = e; sum += e; }
      float inv = 1.f/sum;
      for (int m = 0; m < MW; ++m) s_att[m] *= inv;
      for (int j = 0; j < 3; ++j) {     // top-3, lower index wins ties (matches jax top_k)
        float best = -1e30f; int bi = 0;
        for (int m = 0; m < MW; ++m) if (s_att[m] > best) { best = s_att[m]; bi = m; }
        s_v[j] = best; s_idx[j] = bi; s_att[bi] = -1e30f;
      }
    }
    __syncthreads();
    float tau = s_tau;
    if (tid < QD) {
      float old = s_v[0]*W[tid*MW+s_idx[0]] + s_v[1]*W[tid*MW+s_idx[1]] + s_v[2]*W[tid*MW+s_idx[2]];
      s_q[tid] = tau*s_q[tid] + (1.f-tau)*old;
    }
    __syncthreads();
  }

  // ---- emit bias + fragment-ordered A into sAf (overwrites ctrl_w staging) ----
  if (tid < O_) sBias[tid] = conv_b[tid]*s_q[192+tid]*s_q[256+tid];
  #pragma unroll 4
  for (int idx = tid; idx < O_*KDIM; idx += CONV_THREADS) {
    int o = idx / KDIM;
    int r = idx - o*KDIM;
    int i = r / 3;
    int k = r - i*3;
    float v = conv_w[idx] * s_q[o*3+k] * s_q[256+o];
    int kap = k*64 + i;
    int kk = kap >> 3, c = kap & 7;
    int t4 = c & 3, half = c >> 2;
    int wm = o >> 5, mt = (o >> 4) & 1, g = o & 7, rh = (o >> 3) & 1;
    int fi = ((((wm*24 + kk)*2 + mt)*32) + (g*4 + t4))*4 + half*2 + rh;
    sAf[fi] = __uint_as_float(f2tf32(v));
  }
  __syncthreads();

  // ================== NOW start the x pipeline ==================
  prefetch_tile(x, start, sX0, tid);
  asm volatile("cp.async.commit_group;");
  if (start + 1 < end) prefetch_tile(x, start+1, sX1, tid);
  asm volatile("cp.async.commit_group;");

  // ================== CONV mainloop ==================
  int wid = tid >> 5, lane = tid & 31;
  int g  = lane >> 2, t4 = lane & 3;
  int warp_m = wid & 1, warp_n = wid >> 1;     // 2 x 8 warps
  const float* sAfw = sAf + warp_m*6144 + lane*4;
  int tloc3 = warp_n*32 + g + 3;

  for (int ti = start; ti < end; ++ti) {
    float* sx = ((ti - start) & 1) ? sX1 : sX0;
    if (ti + 1 < end) { asm volatile("cp.async.wait_group 1;"); }
    else              { asm volatile("cp.async.wait_group 0;"); }
    __syncthreads();

    // ---- one-pass in-place tf32 rounding of the tile (idempotent for MMA) ----
    {
      float4* p = reinterpret_cast<float4*>(sx);
      #pragma unroll
      for (int j = 0; j < 9; ++j) {
        int i4 = tid + j*CONV_THREADS;
        if (i4 < XT_FLOATS/4) {
          float4 v = p[i4];
          v.x = f2tf32f(v.x); v.y = f2tf32f(v.y);
          v.z = f2tf32f(v.z); v.w = f2tf32f(v.w);
          p[i4] = v;
        }
      }
    }
    __syncthreads();

    float c[2][4][4];
    #pragma unroll
    for (int mt = 0; mt < 2; ++mt)
      #pragma unroll
      for (int nt = 0; nt < 4; ++nt)
        { c[mt][nt][0]=0.f; c[mt][nt][1]=0.f; c[mt][nt][2]=0.f; c[mt][nt][3]=0.f; }

    const float* pB = sx + t4*XS + tloc3;

    #pragma unroll
    for (int kk = 0; kk < 24; ++kk) {
      const int ktap = kk >> 3;   // compile-time after unroll
      const int ic   = kk & 7;
      float4 a0 = *reinterpret_cast<const float4*>(sAfw + (kk*2+0)*128);
      float4 a1 = *reinterpret_cast<const float4*>(sAfw + (kk*2+1)*128);
      const float* pb = pB + ic*(8*XS) + ktap;
      uint32_t b0[4], b1[4];
      #pragma unroll
      for (int nt = 0; nt < 4; ++nt) {
        b0[nt] = __float_as_uint(pb[nt*8]);          // already tf32-rounded
        b1[nt] = __float_as_uint(pb[4*XS + nt*8]);
      }
      #pragma unroll
      for (int nt = 0; nt < 4; ++nt) {
        asm("mma.sync.aligned.m16n8k8.row.col.f32.tf32.tf32.f32 "
            "{%0,%1,%2,%3}, {%4,%5,%6,%7}, {%8,%9}, {%0,%1,%2,%3};"
            : "+f"(c[0][nt][0]), "+f"(c[0][nt][1]), "+f"(c[0][nt][2]), "+f"(c[0][nt][3])
            : "r"(__float_as_uint(a0.x)), "r"(__float_as_uint(a0.y)),
              "r"(__float_as_uint(a0.z)), "r"(__float_as_uint(a0.w)),
              "r"(b0[nt]), "r"(b1[nt]));
        asm("mma.sync.aligned.m16n8k8.row.col.f32.tf32.tf32.f32 "
            "{%0,%1,%2,%3}, {%4,%5,%6,%7}, {%8,%9}, {%0,%1,%2,%3};"
            : "+f"(c[1][nt][0]), "+f"(c[1][nt][1]), "+f"(c[1][nt][2]), "+f"(c[1][nt][3])
            : "r"(__float_as_uint(a1.x)), "r"(__float_as_uint(a1.y)),
              "r"(__float_as_uint(a1.z)), "r"(__float_as_uint(a1.w)),
              "r"(b0[nt]), "r"(b1[nt]));
      }
    }
    __syncthreads();  // done reading sx

    if (ti + 2 < end) {
      prefetch_tile(x, ti+2, sx, tid);
      asm volatile("cp.async.commit_group;");
    }

    // epilogue
    int bb = ti >> 5;
    int t0 = (ti & 31) << 8;
    float* outb = out + (size_t)bb*(O_*T_) + t0 + warp_n*32 + t4*2;
    #pragma unroll
    for (int mt = 0; mt < 2; ++mt) {
      int o0 = warp_m*32 + mt*16 + g;
      float bv0 = sBias[o0], bv1 = sBias[o0+8];
      float* p0 = outb + (size_t)o0*T_;
      float* p1 = p0 + (size_t)8*T_;
      #pragma unroll
      for (int nt = 0; nt < 4; ++nt) {
        *reinterpret_cast<float2*>(p0 + nt*8) = make_float2(c[mt][nt][0]+bv0, c[mt][nt][1]+bv0);
        *reinterpret_cast<float2*>(p1 + nt*8) = make_float2(c[mt][nt][2]+bv1, c[mt][nt][3]+bv1);
      }
    }
  }
}

// -------------------- launch --------------------
extern "C" void kernel_launch(void* const* d_in, const int* in_sizes, int n_in,
                              void* d_out, int out_size) {
  const float* x      = (const float*)d_in[0];
  const float* grads  = (const float*)d_in[1];
  const float* q_ema  = (const float*)d_in[2];
  const float* W      = (const float*)d_in[3];
  const float* conv_w = (const float*)d_in[4];
  const float* conv_b = (const float*)d_in[5];
  const float* ctrl_w = (const float*)d_in[6];
  const float* ctrl_b = (const float*)d_in[7];
  const float* cw_w   = (const float*)d_in[8];
  const float* cw_b   = (const float*)d_in[9];
  const float* cb_w   = (const float*)d_in[10];
  const float* cb_b   = (const float*)d_in[11];
  const float* cf_w   = (const float*)d_in[12];
  const float* cf_b   = (const float*)d_in[13];
  const float* tau_w1 = (const float*)d_in[14];
  const float* tau_b1 = (const float*)d_in[15];
  const float* tau_w2 = (const float*)d_in[16];
  const float* tau_b2 = (const float*)d_in[17];
  const int*   trig   = (const int*)d_in[18];
  float* out = (float*)d_out;

  cudaFuncSetAttribute(fused_kernel, cudaFuncAttributeMaxDynamicSharedMemorySize, SMEM_BYTES);
  fused_kernel<<<GRID, CONV_THREADS, SMEM_BYTES>>>(x, out, grads, q_ema, W, conv_w, conv_b,
      ctrl_w, ctrl_b, cw_w, cw_b, cb_w, cb_b, cf_w, cf_b,
      tau_w1, tau_b1, tau_w2, tau_b2, trig);
}

// round 16
// speedup vs baseline: 1.1333x; 1.1256x over previous
#include <cuda_runtime.h>
#include <cstdint>

#define B_ 64
#define I_ 64
#define O_ 64
#define T_ 8192
#define KDIM 192      // I_*3
#define NH 64
#define MW 32
#define QD 320

#define TT 256
#define XS 264                 // x tile row stride: 264 % 32 == 8 -> conflict-free
#define CONV_THREADS 512
#define GRID 152
#define TILES_TOTAL (B_*(T_/TT))   // 2048
#define AF_FLOATS 12288        // A fragment region
#define XT_FLOATS (I_*XS)      // 16896
#define SMEM_FLOATS (AF_FLOATS + 64 + 2*XT_FLOATS)   // 46144
#define SMEM_BYTES (SMEM_FLOATS*4)                   // 184576
#define GS 196                 // grads/ctrl_w staging stride (196 % 32 == 4)

__device__ __forceinline__ float sigmoidf_(float x){ return 1.f/(1.f+expf(-x)); }
__device__ __forceinline__ float siluf_(float x){ return x * sigmoidf_(x); }
__device__ __forceinline__ uint32_t f2tf32(float x){
  uint32_t r; asm("cvt.rna.tf32.f32 %0, %1;" : "=r"(r) : "f"(x)); return r;
}
__device__ __forceinline__ float f2tf32f(float x){
  uint32_t r; asm("cvt.rna.tf32.f32 %0, %1;" : "=r"(r) : "f"(x));
  return __uint_as_float(r);
}

__device__ __forceinline__ void prefetch_tile(const float* __restrict__ x, int ti,
                                              float* __restrict__ sXb, int tid) {
  int bb = ti >> 5;
  int t0 = (ti & 31) << 8;
  const float* xb = x + (size_t)bb * (I_*T_);
  #pragma unroll
  for (int j = 0; j < 9; ++j) {
    int c = tid + j*CONV_THREADS;
    if (c < I_*66) {
      int row = c / 66;
      int jc = c - 66*row;
      int tg = t0 - 4 + jc*4;
      float* dst = sXb + row*XS + jc*4;
      if (tg >= 0 && tg <= T_-4) {
        unsigned sa = (unsigned)__cvta_generic_to_shared(dst);
        asm volatile("cp.async.cg.shared.global [%0], [%1], 16;"
                     :: "r"(sa), "l"(xb + (size_t)row*T_ + tg));
      } else {
        *reinterpret_cast<float4*>(dst) = make_float4(0.f,0.f,0.f,0.f);
      }
    }
  }
}

__global__ __launch_bounds__(CONV_THREADS, 1)
void fused_kernel(const float* __restrict__ x, float* __restrict__ out,
    const float* __restrict__ grads, const float* __restrict__ q_ema,
    const float* __restrict__ W,
    const float* __restrict__ conv_w, const float* __restrict__ conv_b,
    const float* __restrict__ ctrl_w, const float* __restrict__ ctrl_b,
    const float* __restrict__ cw_w, const float* __restrict__ cw_b,
    const float* __restrict__ cb_w, const float* __restrict__ cb_b,
    const float* __restrict__ cf_w, const float* __restrict__ cf_b,
    const float* __restrict__ tau_w1, const float* __restrict__ tau_b1,
    const float* __restrict__ tau_w2, const float* __restrict__ tau_b2,
    const int* __restrict__ trigger)
{
  extern __shared__ float smem[];
  float* sAf   = smem;                   // A fragments (conv)
  float* sBias = smem + AF_FLOATS;       // [64]
  float* sX0   = sBias + 64;             // [64][264]; prep: grads staging [64][196]
  float* sX1   = sX0 + XT_FLOATS;        //            prep: ctrl_w staging [64][196]

  __shared__ float s_rep[O_*68];
  __shared__ float s_q[QD];
  __shared__ float s_red[O_];
  __shared__ float s_tau;
  __shared__ float s_part[16*33];
  __shared__ int   s_idx[3];
  __shared__ float s_v[3];

  int tid = threadIdx.x, bid = blockIdx.x;
  int start = (int)(((long long)bid    *TILES_TOTAL)/GRID);
  int end   = (int)(((long long)(bid+1)*TILES_TOTAL)/GRID);

  int wid = tid >> 5, lane = tid & 31;
  int g  = lane >> 2, t4 = lane & 3;

  // ================== PREP ==================

  // ---- stage grads -> sX0, ctrl_w -> sX1 (both [64][196], tf32-rounded) ----
  for (int i4 = tid; i4 < O_*48; i4 += CONV_THREADS) {
    int row = i4 / 48, c4 = i4 - row*48;
    float4 gv = reinterpret_cast<const float4*>(grads)[i4];
    gv.x = f2tf32f(gv.x); gv.y = f2tf32f(gv.y); gv.z = f2tf32f(gv.z); gv.w = f2tf32f(gv.w);
    *reinterpret_cast<float4*>(&sX0[row*GS + c4*4]) = gv;
    float4 wv = reinterpret_cast<const float4*>(ctrl_w)[i4];
    wv.x = f2tf32f(wv.x); wv.y = f2tf32f(wv.y); wv.z = f2tf32f(wv.z); wv.w = f2tf32f(wv.w);
    *reinterpret_cast<float4*>(&sX1[row*GS + c4*4]) = wv;
  }
  __syncthreads();

  // ---- rep = silu(G @ ctrlW^T + b) via tf32 MMA: M=64(o) x N=64(h) x K=192 ----
  {
    int wm2 = wid & 1, wn2 = wid >> 1;       // 2 x 8 warps
    float c[2][4];
    #pragma unroll
    for (int mt = 0; mt < 2; ++mt)
      { c[mt][0]=0.f; c[mt][1]=0.f; c[mt][2]=0.f; c[mt][3]=0.f; }
    int hb = wn2*8;
    #pragma unroll 4
    for (int kk = 0; kk < 24; ++kk) {
      int col = kk*8 + t4;
      uint32_t b0 = __float_as_uint(sX1[(hb+g)*GS + col]);
      uint32_t b1 = __float_as_uint(sX1[(hb+g)*GS + col + 4]);
      #pragma unroll
      for (int mt = 0; mt < 2; ++mt) {
        const float* pa = sX0 + (wm2*32 + mt*16 + g)*GS + col;
        uint32_t a0 = __float_as_uint(pa[0]);
        uint32_t a1 = __float_as_uint(pa[8*GS]);
        uint32_t a2 = __float_as_uint(pa[4]);
        uint32_t a3 = __float_as_uint(pa[8*GS+4]);
        asm("mma.sync.aligned.m16n8k8.row.col.f32.tf32.tf32.f32 "
            "{%0,%1,%2,%3}, {%4,%5,%6,%7}, {%8,%9}, {%0,%1,%2,%3};"
            : "+f"(c[mt][0]), "+f"(c[mt][1]), "+f"(c[mt][2]), "+f"(c[mt][3])
            : "r"(a0), "r"(a1), "r"(a2), "r"(a3), "r"(b0), "r"(b1));
      }
    }
    // C frag: c0,c1 -> row g,  cols 2*t4, 2*t4+1 ; c2,c3 -> row g+8
    #pragma unroll
    for (int mt = 0; mt < 2; ++mt) {
      int o0 = wm2*32 + mt*16 + g;
      int h0 = wn2*8 + t4*2;
      s_rep[o0*68     + h0    ] = siluf_(c[mt][0] + ctrl_b[h0]);
      s_rep[o0*68     + h0 + 1] = siluf_(c[mt][1] + ctrl_b[h0+1]);
      s_rep[(o0+8)*68 + h0    ] = siluf_(c[mt][2] + ctrl_b[h0]);
      s_rep[(o0+8)*68 + h0 + 1] = siluf_(c[mt][3] + ctrl_b[h0+1]);
    }
  }
  __syncthreads();

  // ---- heads ----
  if (tid < 192) {                 // w head
    int o = tid/3, k = tid - 3*(tid/3);
    const float* r = s_rep + o*68;
    const float* w = cw_w + k*NH;
    float s = cw_b[k];
    #pragma unroll 8
    for (int h = 0; h < NH; ++h) s += r[h]*w[h];
    s_q[o*3+k] = s;
  } else if (tid < 256) {          // b head
    int o = tid - 192;
    const float* r = s_rep + o*68;
    float s = cb_b[0];
    #pragma unroll 8
    for (int h = 0; h < NH; ++h) s += r[h]*cb_w[h];
    s_q[192+o] = s;
  } else if (tid < 320) {          // f head
    int o = tid - 256;
    const float* r = s_rep + o*68;
    float s = cf_b[0];
    #pragma unroll 8
    for (int h = 0; h < NH; ++h) s += r[h]*cf_w[h];
    s_q[256+o] = s;
  } else if (tid < 384) {          // tau head
    int o = tid - 320;
    const float* r = s_rep + o*68;
    float acc = tau_b2[0];
    for (int j = 0; j < 16; ++j) {
      float s = tau_b1[j];
      const float* w = tau_w1 + j*NH;
      #pragma unroll 8
      for (int h = 0; h < NH; ++h) s += r[h]*w[h];
      acc += siluf_(s)*tau_w2[j];
    }
    s_red[o] = sigmoidf_(acc);
  }
  __syncthreads();
  if (tid == 0) {
    float m = 0.f;
    for (int o = 0; o < O_; ++o) m += s_red[o];
    s_tau = (m * (1.f/64.f))*0.5f + 0.5f;
  }
  __syncthreads();

  if (tid < QD) s_q[tid] = 0.85f*s_q[tid] + 0.15f*q_ema[tid];  // EMA mix
  __syncthreads();

  if (trigger[0] == 1) {
    // ---- att matvec: 16 segments x 32 m, deterministic tree reduce ----
    {
      int m = tid & 31, seg = tid >> 5;    // seg 0..15, 20 d's each
      float p = 0.f;
      int d0 = seg*20;
      #pragma unroll 5
      for (int d = d0; d < d0+20; ++d) p += s_q[d]*W[d*MW + m];
      s_part[seg*33 + m] = p;
    }
    __syncthreads();
    if (tid < 32) {
      float v = 0.f;
      #pragma unroll
      for (int s = 0; s < 16; ++s) v += s_part[s*33 + tid];   // fixed order
      v *= 2.0f;                                              // / TEMP (0.5)
      // warp softmax
      float mx = v;
      #pragma unroll
      for (int off = 16; off > 0; off >>= 1) mx = fmaxf(mx, __shfl_xor_sync(0xffffffffu, mx, off));
      float e = expf(v - mx);
      float sum = e;
      #pragma unroll
      for (int off = 16; off > 0; off >>= 1) sum += __shfl_xor_sync(0xffffffffu, sum, off);
      float a = e / sum;
      // top-3 via argmax butterfly; ties -> lower index (matches jax top_k)
      #pragma unroll
      for (int j = 0; j < 3; ++j) {
        float bv = a; int bi = tid;
        #pragma unroll
        for (int off = 16; off > 0; off >>= 1) {
          float ov = __shfl_xor_sync(0xffffffffu, bv, off);
          int   oi = __shfl_xor_sync(0xffffffffu, bi, off);
          if (ov > bv || (ov == bv && oi < bi)) { bv = ov; bi = oi; }
        }
        if (tid == 0) { s_v[j] = bv; s_idx[j] = bi; }
        if (tid == bi) a = -1e30f;
      }
    }
    __syncthreads();
    float tau = s_tau;
    if (tid < QD) {
      float old = s_v[0]*W[tid*MW+s_idx[0]] + s_v[1]*W[tid*MW+s_idx[1]] + s_v[2]*W[tid*MW+s_idx[2]];
      s_q[tid] = tau*s_q[tid] + (1.f-tau)*old;
    }
    __syncthreads();
  }

  // ---- emit bias + fragment-ordered A into sAf ----
  if (tid < O_) sBias[tid] = conv_b[tid]*s_q[192+tid]*s_q[256+tid];
  #pragma unroll 4
  for (int idx = tid; idx < O_*KDIM; idx += CONV_THREADS) {
    int o = idx / KDIM;
    int r = idx - o*KDIM;
    int i = r / 3;
    int k = r - i*3;
    float v = conv_w[idx] * s_q[o*3+k] * s_q[256+o];
    int kap = k*64 + i;
    int kk = kap >> 3, c = kap & 7;
    int tt4 = c & 3, half = c >> 2;
    int wm = o >> 5, mt = (o >> 4) & 1, gg = o & 7, rh = (o >> 3) & 1;
    int fi = ((((wm*24 + kk)*2 + mt)*32) + (gg*4 + tt4))*4 + half*2 + rh;
    sAf[fi] = __uint_as_float(f2tf32(v));
  }
  __syncthreads();

  // ================== x pipeline ==================
  prefetch_tile(x, start, sX0, tid);
  asm volatile("cp.async.commit_group;");
  if (start + 1 < end) prefetch_tile(x, start+1, sX1, tid);
  asm volatile("cp.async.commit_group;");

  // ================== CONV mainloop (verified) ==================
  int warp_m = wid & 1, warp_n = wid >> 1;     // 2 x 8 warps
  const float* sAfw = sAf + warp_m*6144 + lane*4;
  int tloc3 = warp_n*32 + g + 3;

  for (int ti = start; ti < end; ++ti) {
    float* sx = ((ti - start) & 1) ? sX1 : sX0;
    if (ti + 1 < end) { asm volatile("cp.async.wait_group 1;"); }
    else              { asm volatile("cp.async.wait_group 0;"); }
    __syncthreads();

    // one-pass in-place tf32 rounding of the tile (idempotent for MMA)
    {
      float4* p = reinterpret_cast<float4*>(sx);
      #pragma unroll
      for (int j = 0; j < 9; ++j) {
        int i4 = tid + j*CONV_THREADS;
        if (i4 < XT_FLOATS/4) {
          float4 v = p[i4];
          v.x = f2tf32f(v.x); v.y = f2tf32f(v.y);
          v.z = f2tf32f(v.z); v.w = f2tf32f(v.w);
          p[i4] = v;
        }
      }
    }
    __syncthreads();

    float c[2][4][4];
    #pragma unroll
    for (int mt = 0; mt < 2; ++mt)
      #pragma unroll
      for (int nt = 0; nt < 4; ++nt)
        { c[mt][nt][0]=0.f; c[mt][nt][1]=0.f; c[mt][nt][2]=0.f; c[mt][nt][3]=0.f; }

    const float* pB = sx + t4*XS + tloc3;

    #pragma unroll
    for (int kk = 0; kk < 24; ++kk) {
      const int ktap = kk >> 3;
      const int ic   = kk & 7;
      float4 a0 = *reinterpret_cast<const float4*>(sAfw + (kk*2+0)*128);
      float4 a1 = *reinterpret_cast<const float4*>(sAfw + (kk*2+1)*128);
      const float* pb = pB + ic*(8*XS) + ktap;
      uint32_t b0[4], b1[4];
      #pragma unroll
      for (int nt = 0; nt < 4; ++nt) {
        b0[nt] = __float_as_uint(pb[nt*8]);
        b1[nt] = __float_as_uint(pb[4*XS + nt*8]);
      }
      #pragma unroll
      for (int nt = 0; nt < 4; ++nt) {
        asm("mma.sync.aligned.m16n8k8.row.col.f32.tf32.tf32.f32 "
            "{%0,%1,%2,%3}, {%4,%5,%6,%7}, {%8,%9}, {%0,%1,%2,%3};"
            : "+f"(c[0][nt][0]), "+f"(c[0][nt][1]), "+f"(c[0][nt][2]), "+f"(c[0][nt][3])
            : "r"(__float_as_uint(a0.x)), "r"(__float_as_uint(a0.y)),
              "r"(__float_as_uint(a0.z)), "r"(__float_as_uint(a0.w)),
              "r"(b0[nt]), "r"(b1[nt]));
        asm("mma.sync.aligned.m16n8k8.row.col.f32.tf32.tf32.f32 "
            "{%0,%1,%2,%3}, {%4,%5,%6,%7}, {%8,%9}, {%0,%1,%2,%3};"
            : "+f"(c[1][nt][0]), "+f"(c[1][nt][1]), "+f"(c[1][nt][2]), "+f"(c[1][nt][3])
            : "r"(__float_as_uint(a1.x)), "r"(__float_as_uint(a1.y)),
              "r"(__float_as_uint(a1.z)), "r"(__float_as_uint(a1.w)),
              "r"(b0[nt]), "r"(b1[nt]));
      }
    }
    __syncthreads();  // done reading sx

    if (ti + 2 < end) {
      prefetch_tile(x, ti+2, sx, tid);
      asm volatile("cp.async.commit_group;");
    }

    // epilogue
    int bb = ti >> 5;
    int t0 = (ti & 31) << 8;
    float* outb = out + (size_t)bb*(O_*T_) + t0 + warp_n*32 + t4*2;
    #pragma unroll
    for (int mt = 0; mt < 2; ++mt) {
      int o0 = warp_m*32 + mt*16 + g;
      float bv0 = sBias[o0], bv1 = sBias[o0+8];
      float* p0 = outb + (size_t)o0*T_;
      float* p1 = p0 + (size_t)8*T_;
      #pragma unroll
      for (int nt = 0; nt < 4; ++nt) {
        *reinterpret_cast<float2*>(p0 + nt*8) = make_float2(c[mt][nt][0]+bv0, c[mt][nt][1]+bv0);
        *reinterpret_cast<float2*>(p1 + nt*8) = make_float2(c[mt][nt][2]+bv1, c[mt][nt][3]+bv1);
      }
    }
  }
}

// -------------------- launch --------------------
extern "C" void kernel_launch(void* const* d_in, const int* in_sizes, int n_in,
                              void* d_out, int out_size) {
  const float* x      = (const float*)d_in[0];
  const float* grads  = (const float*)d_in[1];
  const float* q_ema  = (const float*)d_in[2];
  const float* W      = (const float*)d_in[3];
  const float* conv_w = (const float*)d_in[4];
  const float* conv_b = (const float*)d_in[5];
  const float* ctrl_w = (const float*)d_in[6];
  const float* ctrl_b = (const float*)d_in[7];
  const float* cw_w   = (const float*)d_in[8];
  const float* cw_b   = (const float*)d_in[9];
  const float* cb_w   = (const float*)d_in[10];
  const float* cb_b   = (const float*)d_in[11];
  const float* cf_w   = (const float*)d_in[12];
  const float* cf_b   = (const float*)d_in[13];
  const float* tau_w1 = (const float*)d_in[14];
  const float* tau_b1 = (const float*)d_in[15];
  const float* tau_w2 = (const float*)d_in[16];
  const float* tau_b2 = (const float*)d_in[17];
  const int*   trig   = (const int*)d_in[18];
  float* out = (float*)d_out;

  cudaFuncSetAttribute(fused_kernel, cudaFuncAttributeMaxDynamicSharedMemorySize, SMEM_BYTES);
  fused_kernel<<<GRID, CONV_THREADS, SMEM_BYTES>>>(x, out, grads, q_ema, W, conv_w, conv_b,
      ctrl_w, ctrl_b, cw_w, cw_b, cb_w, cb_b, cf_w, cf_b,
      tau_w1, tau_b1, tau_w2, tau_b2, trig);
}